// round 1
// baseline (speedup 1.0000x reference)
#include <cuda_runtime.h>
#include <math.h>

// Problem constants
#define BN 4
#define TN 2048
#define DN 1024
#define HN 16
#define HDN 64
#define BTN (BN * TN)
#define QK_SCALE 0.03125f  // 1/sqrt(1024)

// Scratch (static device allocations: allowed)
__device__ float g_q[BN * HN * TN * HDN];
__device__ float g_k[BN * HN * TN * HDN];
__device__ float g_v[BN * HN * TN * HDN];
__device__ float g_attn[BTN * DN];

// ---------------------------------------------------------------------------
// Kernel 1: QKV projections.
// grid = (BT/64, H, 3), block = 256 (16x16), 64x64 output tile per block,
// K = 1024 in chunks of 16. Output layout: [b][h][t][e] contiguous per (b,h).
// ---------------------------------------------------------------------------
__global__ __launch_bounds__(256) void qkv_kernel(
    const float* __restrict__ data, const float* __restrict__ Wq,
    const float* __restrict__ Wk, const float* __restrict__ Wv) {
  __shared__ float As[16][65];  // [k][m]
  __shared__ float Bs[16][65];  // [k][n]

  const int tid = threadIdx.x;
  const int h = blockIdx.y;
  const int m0 = blockIdx.x * 64;

  const float* W;
  float* out;
  if (blockIdx.z == 0) { W = Wq; out = g_q; }
  else if (blockIdx.z == 1) { W = Wk; out = g_k; }
  else { W = Wv; out = g_v; }
  W += (size_t)h * DN * HDN;

  const int tx = tid & 15, ty = tid >> 4;
  const int ar = tid >> 2, ak = (tid & 3) * 4;   // A tile: 64 rows x 16 k
  const int br = tid >> 4, bc = (tid & 15) * 4;  // B tile: 16 k x 64 e

  float acc[4][4] = {};
  for (int k0 = 0; k0 < DN; k0 += 16) {
    float4 a = *(const float4*)(data + (size_t)(m0 + ar) * DN + k0 + ak);
    As[ak + 0][ar] = a.x; As[ak + 1][ar] = a.y;
    As[ak + 2][ar] = a.z; As[ak + 3][ar] = a.w;
    float4 bvec = *(const float4*)(W + (size_t)(k0 + br) * HDN + bc);
    Bs[br][bc + 0] = bvec.x; Bs[br][bc + 1] = bvec.y;
    Bs[br][bc + 2] = bvec.z; Bs[br][bc + 3] = bvec.w;
    __syncthreads();
#pragma unroll
    for (int k = 0; k < 16; k++) {
      float av[4], bv[4];
#pragma unroll
      for (int i = 0; i < 4; i++) av[i] = As[k][ty * 4 + i];
#pragma unroll
      for (int j = 0; j < 4; j++) bv[j] = Bs[k][tx * 4 + j];
#pragma unroll
      for (int i = 0; i < 4; i++)
#pragma unroll
        for (int j = 0; j < 4; j++) acc[i][j] += av[i] * bv[j];
    }
    __syncthreads();
  }

  const int b = m0 >> 11;           // T = 2048
  const int tbase = m0 & (TN - 1);  // tiles never cross batch boundary
#pragma unroll
  for (int i = 0; i < 4; i++) {
    float* orow =
        out + ((size_t)((b * HN + h) * TN + tbase + ty * 4 + i)) * HDN + tx * 4;
#pragma unroll
    for (int j = 0; j < 4; j++) orow[j] = acc[i][j];
  }
}

// ---------------------------------------------------------------------------
// Kernel 2: causal flash attention per (b,h).
// grid = (T/64, B*H), block = 256. 64 query rows per block, key tiles of 64,
// online softmax. Scale folded into Q load. Writes concat layout [bt][h*64+e].
// ---------------------------------------------------------------------------
__global__ __launch_bounds__(256) void attn_kernel() {
  extern __shared__ float sm[];
  float(*Qs)[65] = (float(*)[65])(sm);
  float(*Ks)[65] = (float(*)[65])(sm + 64 * 65);
  float(*Vs)[65] = (float(*)[65])(sm + 2 * 64 * 65);
  float(*Ps)[65] = (float(*)[65])(sm + 3 * 64 * 65);

  const int tid = threadIdx.x;
  const int bh = blockIdx.y;
  const int m0 = blockIdx.x * 64;
  const int tx = tid & 15, ty = tid >> 4;

  const float* qb = g_q + (size_t)bh * TN * HDN;
  const float* kb = g_k + (size_t)bh * TN * HDN;
  const float* vb = g_v + (size_t)bh * TN * HDN;

  // Load + scale Q tile (64x64)
#pragma unroll
  for (int u = 0; u < 4; u++) {
    int i = tid + u * 256;
    int r = i >> 4, c4 = (i & 15) * 4;
    float4 q4 = *(const float4*)(qb + (size_t)(m0 + r) * HDN + c4);
    Qs[r][c4 + 0] = q4.x * QK_SCALE;
    Qs[r][c4 + 1] = q4.y * QK_SCALE;
    Qs[r][c4 + 2] = q4.z * QK_SCALE;
    Qs[r][c4 + 3] = q4.w * QK_SCALE;
  }

  float m_i[4], l_i[4], o[4][4] = {};
#pragma unroll
  for (int i = 0; i < 4; i++) { m_i[i] = -INFINITY; l_i[i] = 0.0f; }

  const int jmax = blockIdx.x;  // causal: key tile <= query tile
  for (int j = 0; j <= jmax; j++) {
    const int n0 = j * 64;
    // Load K, V tiles
#pragma unroll
    for (int u = 0; u < 4; u++) {
      int i = tid + u * 256;
      int r = i >> 4, c4 = (i & 15) * 4;
      float4 k4 = *(const float4*)(kb + (size_t)(n0 + r) * HDN + c4);
      Ks[r][c4 + 0] = k4.x; Ks[r][c4 + 1] = k4.y;
      Ks[r][c4 + 2] = k4.z; Ks[r][c4 + 3] = k4.w;
      float4 v4 = *(const float4*)(vb + (size_t)(n0 + r) * HDN + c4);
      Vs[r][c4 + 0] = v4.x; Vs[r][c4 + 1] = v4.y;
      Vs[r][c4 + 2] = v4.z; Vs[r][c4 + 3] = v4.w;
    }
    __syncthreads();

    // S = Q K^T  (4x4 per thread)
    float s[4][4] = {};
#pragma unroll 8
    for (int e = 0; e < 64; e++) {
      float qv[4], kv[4];
#pragma unroll
      for (int i = 0; i < 4; i++) qv[i] = Qs[ty * 4 + i][e];
#pragma unroll
      for (int jj = 0; jj < 4; jj++) kv[jj] = Ks[tx * 4 + jj][e];
#pragma unroll
      for (int i = 0; i < 4; i++)
#pragma unroll
        for (int jj = 0; jj < 4; jj++) s[i][jj] += qv[i] * kv[jj];
    }

    // Causal mask on the diagonal tile only
    if (n0 == m0) {
#pragma unroll
      for (int i = 0; i < 4; i++)
#pragma unroll
        for (int jj = 0; jj < 4; jj++)
          if (tx * 4 + jj > ty * 4 + i) s[i][jj] = -INFINITY;
    }

    // Row max (reduce across the 16 tx lanes; xor<=8 stays within the group)
    float rmax[4];
#pragma unroll
    for (int i = 0; i < 4; i++) {
      float v = fmaxf(fmaxf(s[i][0], s[i][1]), fmaxf(s[i][2], s[i][3]));
#pragma unroll
      for (int off = 8; off > 0; off >>= 1)
        v = fmaxf(v, __shfl_xor_sync(0xffffffffu, v, off));
      rmax[i] = v;
    }

    float rsum[4];
#pragma unroll
    for (int i = 0; i < 4; i++) {
      float mnew = fmaxf(m_i[i], rmax[i]);
      float corr = __expf(m_i[i] - mnew);  // exp(-inf)=0 on first tile
      float rs = 0.0f;
#pragma unroll
      for (int jj = 0; jj < 4; jj++) {
        float p = __expf(s[i][jj] - mnew);
        Ps[ty * 4 + i][tx * 4 + jj] = p;
        rs += p;
      }
#pragma unroll
      for (int off = 8; off > 0; off >>= 1)
        rs += __shfl_xor_sync(0xffffffffu, rs, off);
      rsum[i] = rs;
      l_i[i] = l_i[i] * corr + rs;
      m_i[i] = mnew;
#pragma unroll
      for (int jj = 0; jj < 4; jj++) o[i][jj] *= corr;
    }
    __syncthreads();  // Ps visible

    // O += P V
#pragma unroll 8
    for (int s2 = 0; s2 < 64; s2++) {
      float pv[4], vv[4];
#pragma unroll
      for (int i = 0; i < 4; i++) pv[i] = Ps[ty * 4 + i][s2];
#pragma unroll
      for (int jj = 0; jj < 4; jj++) vv[jj] = Vs[s2][tx * 4 + jj];
#pragma unroll
      for (int i = 0; i < 4; i++)
#pragma unroll
        for (int jj = 0; jj < 4; jj++) o[i][jj] += pv[i] * vv[jj];
    }
    __syncthreads();  // before next tile overwrites K/V/P
  }

  // Epilogue: O /= l, write concat layout [b*T+t][h*64+e]
  const int b = bh >> 4, h = bh & 15;
#pragma unroll
  for (int i = 0; i < 4; i++) {
    const int t = m0 + ty * 4 + i;
    const float inv = 1.0f / l_i[i];
    float* orow = g_attn + ((size_t)(b * TN + t)) * DN + h * HDN + tx * 4;
#pragma unroll
    for (int jj = 0; jj < 4; jj++) orow[jj] = o[i][jj] * inv;
  }
}

// ---------------------------------------------------------------------------
// Kernel 3: output projection  out = attn @ Wo^T + bo.
// grid = (BT/64, D/64), block = 256. Wo is [n][d] row-major, so both A row
// and B row are contiguous in k.
// ---------------------------------------------------------------------------
__global__ __launch_bounds__(256) void proj_kernel(
    const float* __restrict__ Wo, const float* __restrict__ bo,
    float* __restrict__ out) {
  __shared__ float As[16][65];
  __shared__ float Bs[16][65];

  const int tid = threadIdx.x;
  const int m0 = blockIdx.x * 64;
  const int n0 = blockIdx.y * 64;
  const int tx = tid & 15, ty = tid >> 4;
  const int ar = tid >> 2, ak = (tid & 3) * 4;
  const int bn = tid >> 2, bk = (tid & 3) * 4;

  float acc[4][4] = {};
  for (int k0 = 0; k0 < DN; k0 += 16) {
    float4 a = *(const float4*)(g_attn + (size_t)(m0 + ar) * DN + k0 + ak);
    As[ak + 0][ar] = a.x; As[ak + 1][ar] = a.y;
    As[ak + 2][ar] = a.z; As[ak + 3][ar] = a.w;
    float4 w4 = *(const float4*)(Wo + (size_t)(n0 + bn) * DN + k0 + bk);
    Bs[bk + 0][bn] = w4.x; Bs[bk + 1][bn] = w4.y;
    Bs[bk + 2][bn] = w4.z; Bs[bk + 3][bn] = w4.w;
    __syncthreads();
#pragma unroll
    for (int k = 0; k < 16; k++) {
      float av[4], bv[4];
#pragma unroll
      for (int i = 0; i < 4; i++) av[i] = As[k][ty * 4 + i];
#pragma unroll
      for (int j = 0; j < 4; j++) bv[j] = Bs[k][tx * 4 + j];
#pragma unroll
      for (int i = 0; i < 4; i++)
#pragma unroll
        for (int j = 0; j < 4; j++) acc[i][j] += av[i] * bv[j];
    }
    __syncthreads();
  }

#pragma unroll
  for (int i = 0; i < 4; i++) {
    float* orow = out + (size_t)(m0 + ty * 4 + i) * DN + n0 + tx * 4;
#pragma unroll
    for (int j = 0; j < 4; j++) orow[j] = acc[i][j] + bo[n0 + tx * 4 + j];
  }
}

// ---------------------------------------------------------------------------
extern "C" void kernel_launch(void* const* d_in, const int* in_sizes, int n_in,
                              void* d_out, int out_size) {
  (void)in_sizes; (void)n_in; (void)out_size;
  const float* data = (const float*)d_in[0];
  const float* Wq = (const float*)d_in[1];
  const float* Wk = (const float*)d_in[2];
  const float* Wv = (const float*)d_in[3];
  const float* Wo = (const float*)d_in[4];
  const float* bo = (const float*)d_in[5];
  float* out = (float*)d_out;

  const int attn_smem = 4 * 64 * 65 * (int)sizeof(float);  // 66560 B
  cudaFuncSetAttribute(attn_kernel, cudaFuncAttributeMaxDynamicSharedMemorySize,
                       attn_smem);

  qkv_kernel<<<dim3(BTN / 64, HN, 3), 256>>>(data, Wq, Wk, Wv);
  attn_kernel<<<dim3(TN / 64, BN * HN), 256, attn_smem>>>();
  proj_kernel<<<dim3(BTN / 64, DN / 64), 256>>>(Wo, bo, out);
}

// round 2
// speedup vs baseline: 4.0476x; 4.0476x over previous
#include <cuda_runtime.h>
#include <math.h>

#define BN 4
#define TN 2048
#define DN 1024
#define HN 16
#define HDN 64
#define BTN (BN * TN)
#define QK_SCALE 0.03125f  // 1/sqrt(1024)

// Scratch
__device__ float g_q[BN * HN * TN * HDN];
__device__ float g_k[BN * HN * TN * HDN];
__device__ float g_v[BN * HN * TN * HDN];
__device__ float g_attn[BTN * DN];

__device__ __forceinline__ unsigned cvt_tf32(float x) {
  unsigned u;
  asm("cvt.rna.tf32.f32 %0, %1;" : "=r"(u) : "f"(x));
  return u;
}

__device__ __forceinline__ void mma8(float* c, unsigned a0, unsigned a1,
                                     unsigned a2, unsigned a3, unsigned b0,
                                     unsigned b1) {
  asm volatile(
      "mma.sync.aligned.m16n8k8.row.col.f32.tf32.tf32.f32 "
      "{%0,%1,%2,%3}, {%4,%5,%6,%7}, {%8,%9}, {%0,%1,%2,%3};"
      : "+f"(c[0]), "+f"(c[1]), "+f"(c[2]), "+f"(c[3])
      : "r"(a0), "r"(a1), "r"(a2), "r"(a3), "r"(b0), "r"(b1));
}

// ---------------------------------------------------------------------------
// Kernel 1: QKV projections. C[128,64] tile = data[128,1024] @ W[1024,64].
// grid=(BT/128, H, 3), block=128 (4 warps, 2x2), warp tile 64x32.
// smem strides: As 36 (bank=4m+k), Bs 68 (bank=4k+n) -> conflict-free frags.
// ---------------------------------------------------------------------------
__global__ __launch_bounds__(128) void qkv_kernel(
    const float* __restrict__ data, const float* __restrict__ Wq,
    const float* __restrict__ Wk, const float* __restrict__ Wv) {
  __shared__ unsigned As[128 * 36];  // [m][k], k-pad to 36
  __shared__ unsigned Bs[32 * 68];   // [k][n], n-pad to 68

  const int tid = threadIdx.x;
  const int w = tid >> 5, lane = tid & 31, grp = lane >> 2, qid = lane & 3;
  const int wm = (w >> 1) * 64, wn = (w & 1) * 32;
  const int h = blockIdx.y;
  const int m0 = blockIdx.x * 128;

  const float* W;
  float* out;
  if (blockIdx.z == 0) { W = Wq; out = g_q; }
  else if (blockIdx.z == 1) { W = Wk; out = g_k; }
  else { W = Wv; out = g_v; }
  W += (size_t)h * DN * HDN;

  float c[4][4][4] = {};

  for (int k0 = 0; k0 < DN; k0 += 32) {
#pragma unroll
    for (int u = 0; u < 8; u++) {  // A tile 128x32
      int f = tid + u * 128;
      int row = f >> 3, c4 = (f & 7) * 4;
      float4 a = *(const float4*)(data + (size_t)(m0 + row) * DN + k0 + c4);
      unsigned* p = As + row * 36 + c4;
      p[0] = cvt_tf32(a.x); p[1] = cvt_tf32(a.y);
      p[2] = cvt_tf32(a.z); p[3] = cvt_tf32(a.w);
    }
#pragma unroll
    for (int u = 0; u < 4; u++) {  // B tile 32x64
      int f = tid + u * 128;
      int row = f >> 4, c4 = (f & 15) * 4;
      float4 b = *(const float4*)(W + (size_t)(k0 + row) * HDN + c4);
      unsigned* p = Bs + row * 68 + c4;
      p[0] = cvt_tf32(b.x); p[1] = cvt_tf32(b.y);
      p[2] = cvt_tf32(b.z); p[3] = cvt_tf32(b.w);
    }
    __syncthreads();

#pragma unroll
    for (int kk = 0; kk < 4; kk++) {
      const int k = kk * 8;
      unsigned a[4][4];
#pragma unroll
      for (int mf = 0; mf < 4; mf++) {
        int m = wm + mf * 16;
        a[mf][0] = As[(m + grp) * 36 + k + qid];
        a[mf][1] = As[(m + 8 + grp) * 36 + k + qid];
        a[mf][2] = As[(m + grp) * 36 + k + 4 + qid];
        a[mf][3] = As[(m + 8 + grp) * 36 + k + 4 + qid];
      }
      unsigned b[4][2];
#pragma unroll
      for (int nf = 0; nf < 4; nf++) {
        int n = wn + nf * 8;
        b[nf][0] = Bs[(k + qid) * 68 + n + grp];
        b[nf][1] = Bs[(k + 4 + qid) * 68 + n + grp];
      }
#pragma unroll
      for (int mf = 0; mf < 4; mf++)
#pragma unroll
        for (int nf = 0; nf < 4; nf++)
          mma8(c[mf][nf], a[mf][0], a[mf][1], a[mf][2], a[mf][3], b[nf][0],
               b[nf][1]);
    }
    __syncthreads();
  }

  const int b = m0 >> 11;
  const int tbase = m0 & (TN - 1);
#pragma unroll
  for (int mf = 0; mf < 4; mf++)
#pragma unroll
    for (int i = 0; i < 2; i++) {
      int t = tbase + wm + mf * 16 + grp + 8 * i;
#pragma unroll
      for (int nf = 0; nf < 4; nf++) {
        int e = wn + nf * 8 + 2 * qid;
        float2 v = {c[mf][nf][2 * i], c[mf][nf][2 * i + 1]};
        *(float2*)(out + ((size_t)((b * HN + h) * TN + t)) * HDN + e) = v;
      }
    }
}

// ---------------------------------------------------------------------------
// Kernel 2: causal flash attention. grid=(T/128, B*H), block=128.
// 128 q-rows/block; 4 warps x (32 rows x 64 keys). mma for S and PV.
// ---------------------------------------------------------------------------
__global__ __launch_bounds__(128) void attn_kernel() {
  extern __shared__ unsigned smu[];
  unsigned* Qs = smu;                 // [128][68]
  unsigned* Ks = Qs + 128 * 68;       // [64][68]
  unsigned* Vs = Ks + 64 * 68;        // [64][68]
  unsigned* Ps = Vs + 64 * 68;        // [128][68]

  const int tid = threadIdx.x;
  const int w = tid >> 5, lane = tid & 31, grp = lane >> 2, qid = lane & 3;
  const int bh = blockIdx.y;
  const int m0 = blockIdx.x * 128;
  const int wrow = w * 32;  // warp's q-row offset in block

  const float* qb = g_q + (size_t)bh * TN * HDN;
  const float* kb = g_k + (size_t)bh * TN * HDN;
  const float* vb = g_v + (size_t)bh * TN * HDN;

  // Load Q tile (scaled, tf32)
#pragma unroll
  for (int u = 0; u < 16; u++) {
    int f = tid + u * 128;
    int row = f >> 4, c4 = (f & 15) * 4;
    float4 q = *(const float4*)(qb + (size_t)(m0 + row) * HDN + c4);
    unsigned* p = Qs + row * 68 + c4;
    p[0] = cvt_tf32(q.x * QK_SCALE); p[1] = cvt_tf32(q.y * QK_SCALE);
    p[2] = cvt_tf32(q.z * QK_SCALE); p[3] = cvt_tf32(q.w * QK_SCALE);
  }

  float o[2][8][4] = {};
  float m_i[2][2], l_i[2][2];
#pragma unroll
  for (int mf = 0; mf < 2; mf++)
#pragma unroll
    for (int i = 0; i < 2; i++) { m_i[mf][i] = -INFINITY; l_i[mf][i] = 0.f; }

  const int jmax = 2 * blockIdx.x + 1;
  for (int j = 0; j <= jmax; j++) {
    const int n0g = j * 64;
    // Load K, V tiles (tf32)
#pragma unroll
    for (int u = 0; u < 8; u++) {
      int f = tid + u * 128;
      int row = f >> 4, c4 = (f & 15) * 4;
      float4 k4 = *(const float4*)(kb + (size_t)(n0g + row) * HDN + c4);
      unsigned* pk = Ks + row * 68 + c4;
      pk[0] = cvt_tf32(k4.x); pk[1] = cvt_tf32(k4.y);
      pk[2] = cvt_tf32(k4.z); pk[3] = cvt_tf32(k4.w);
      float4 v4 = *(const float4*)(vb + (size_t)(n0g + row) * HDN + c4);
      unsigned* pv = Vs + row * 68 + c4;
      pv[0] = cvt_tf32(v4.x); pv[1] = cvt_tf32(v4.y);
      pv[2] = cvt_tf32(v4.z); pv[3] = cvt_tf32(v4.w);
    }
    __syncthreads();

    const bool skip = (n0g > m0 + wrow + 31);  // entire tile in the future
    if (!skip) {
      // S = Q K^T
      float s[2][8][4] = {};
#pragma unroll
      for (int kk = 0; kk < 8; kk++) {
        const int k = kk * 8;
        unsigned a[2][4];
#pragma unroll
        for (int mf = 0; mf < 2; mf++) {
          int m = wrow + mf * 16;
          a[mf][0] = Qs[(m + grp) * 68 + k + qid];
          a[mf][1] = Qs[(m + 8 + grp) * 68 + k + qid];
          a[mf][2] = Qs[(m + grp) * 68 + k + 4 + qid];
          a[mf][3] = Qs[(m + 8 + grp) * 68 + k + 4 + qid];
        }
#pragma unroll
        for (int nf = 0; nf < 8; nf++) {
          int n = nf * 8;
          unsigned b0 = Ks[(n + grp) * 68 + k + qid];      // K[n][e]
          unsigned b1 = Ks[(n + grp) * 68 + k + 4 + qid];
#pragma unroll
          for (int mf = 0; mf < 2; mf++)
            mma8(s[mf][nf], a[mf][0], a[mf][1], a[mf][2], a[mf][3], b0, b1);
        }
      }

      // Causal mask (only when tile touches the diagonal for this warp)
      if (n0g + 63 > m0 + wrow) {
#pragma unroll
        for (int mf = 0; mf < 2; mf++)
#pragma unroll
          for (int i = 0; i < 2; i++) {
            int qrow = m0 + wrow + mf * 16 + grp + 8 * i;
#pragma unroll
            for (int nf = 0; nf < 8; nf++) {
              int key = n0g + nf * 8 + 2 * qid;
              if (key > qrow) s[mf][nf][2 * i] = -INFINITY;
              if (key + 1 > qrow) s[mf][nf][2 * i + 1] = -INFINITY;
            }
          }
      }

      // Online softmax per owned row (rows: grp + 8i within each m16 frag)
#pragma unroll
      for (int mf = 0; mf < 2; mf++)
#pragma unroll
        for (int i = 0; i < 2; i++) {
          float v = -INFINITY;
#pragma unroll
          for (int nf = 0; nf < 8; nf++)
            v = fmaxf(v, fmaxf(s[mf][nf][2 * i], s[mf][nf][2 * i + 1]));
          v = fmaxf(v, __shfl_xor_sync(0xffffffffu, v, 1));
          v = fmaxf(v, __shfl_xor_sync(0xffffffffu, v, 2));
          float mnew = fmaxf(m_i[mf][i], v);
          float corr = __expf(m_i[mf][i] - mnew);
          float rs = 0.f;
          int prow = (wrow + mf * 16 + grp + 8 * i) * 68;
#pragma unroll
          for (int nf = 0; nf < 8; nf++) {
            float p0 = __expf(s[mf][nf][2 * i] - mnew);
            float p1 = __expf(s[mf][nf][2 * i + 1] - mnew);
            rs += p0 + p1;
            uint2 pp = {cvt_tf32(p0), cvt_tf32(p1)};
            *(uint2*)(Ps + prow + nf * 8 + 2 * qid) = pp;
          }
          rs += __shfl_xor_sync(0xffffffffu, rs, 1);
          rs += __shfl_xor_sync(0xffffffffu, rs, 2);
          l_i[mf][i] = l_i[mf][i] * corr + rs;
          m_i[mf][i] = mnew;
#pragma unroll
          for (int nf = 0; nf < 8; nf++) {
            o[mf][nf][2 * i] *= corr;
            o[mf][nf][2 * i + 1] *= corr;
          }
        }

      // O += P V   (Ps rows are warp-private; same-warp ordering suffices)
#pragma unroll
      for (int kk = 0; kk < 8; kk++) {
        const int k = kk * 8;
        unsigned a[2][4];
#pragma unroll
        for (int mf = 0; mf < 2; mf++) {
          int m = wrow + mf * 16;
          a[mf][0] = Ps[(m + grp) * 68 + k + qid];
          a[mf][1] = Ps[(m + 8 + grp) * 68 + k + qid];
          a[mf][2] = Ps[(m + grp) * 68 + k + 4 + qid];
          a[mf][3] = Ps[(m + 8 + grp) * 68 + k + 4 + qid];
        }
#pragma unroll
        for (int nf = 0; nf < 8; nf++) {
          int n = nf * 8;
          unsigned b0 = Vs[(k + qid) * 68 + n + grp];  // V[s][e]
          unsigned b1 = Vs[(k + 4 + qid) * 68 + n + grp];
#pragma unroll
          for (int mf = 0; mf < 2; mf++)
            mma8(o[mf][nf], a[mf][0], a[mf][1], a[mf][2], a[mf][3], b0, b1);
        }
      }
    }
    __syncthreads();  // protect K/V before next tile load
  }

  // Epilogue: O /= l, write concat layout [b*T+t][h*64+e]
  const int b = bh >> 4, h = bh & 15;
#pragma unroll
  for (int mf = 0; mf < 2; mf++)
#pragma unroll
    for (int i = 0; i < 2; i++) {
      int t = m0 + wrow + mf * 16 + grp + 8 * i;
      float inv = 1.0f / l_i[mf][i];
#pragma unroll
      for (int nf = 0; nf < 8; nf++) {
        int e = nf * 8 + 2 * qid;
        float2 v = {o[mf][nf][2 * i] * inv, o[mf][nf][2 * i + 1] * inv};
        *(float2*)(g_attn + ((size_t)(b * TN + t)) * DN + h * HDN + e) = v;
      }
    }
}

// ---------------------------------------------------------------------------
// Kernel 3: out = attn @ Wo^T + bo.  grid=(BT/128, D/64), block=128.
// Bs stored [n][k] (B[k][n] = Wo[n][k]); frag bank = 4n+k, conflict-free.
// ---------------------------------------------------------------------------
__global__ __launch_bounds__(128) void proj_kernel(
    const float* __restrict__ Wo, const float* __restrict__ bo,
    float* __restrict__ out) {
  __shared__ unsigned As[128 * 36];  // [m][k]
  __shared__ unsigned Bs[64 * 36];   // [n][k]

  const int tid = threadIdx.x;
  const int w = tid >> 5, lane = tid & 31, grp = lane >> 2, qid = lane & 3;
  const int wm = (w >> 1) * 64, wn = (w & 1) * 32;
  const int m0 = blockIdx.x * 128;
  const int n0 = blockIdx.y * 64;

  float c[4][4][4] = {};

  for (int k0 = 0; k0 < DN; k0 += 32) {
#pragma unroll
    for (int u = 0; u < 8; u++) {
      int f = tid + u * 128;
      int row = f >> 3, c4 = (f & 7) * 4;
      float4 a = *(const float4*)(g_attn + (size_t)(m0 + row) * DN + k0 + c4);
      unsigned* p = As + row * 36 + c4;
      p[0] = cvt_tf32(a.x); p[1] = cvt_tf32(a.y);
      p[2] = cvt_tf32(a.z); p[3] = cvt_tf32(a.w);
    }
#pragma unroll
    for (int u = 0; u < 4; u++) {
      int f = tid + u * 128;
      int n = f >> 3, k4 = (f & 7) * 4;
      float4 b = *(const float4*)(Wo + (size_t)(n0 + n) * DN + k0 + k4);
      unsigned* p = Bs + n * 36 + k4;
      p[0] = cvt_tf32(b.x); p[1] = cvt_tf32(b.y);
      p[2] = cvt_tf32(b.z); p[3] = cvt_tf32(b.w);
    }
    __syncthreads();

#pragma unroll
    for (int kk = 0; kk < 4; kk++) {
      const int k = kk * 8;
      unsigned a[4][4];
#pragma unroll
      for (int mf = 0; mf < 4; mf++) {
        int m = wm + mf * 16;
        a[mf][0] = As[(m + grp) * 36 + k + qid];
        a[mf][1] = As[(m + 8 + grp) * 36 + k + qid];
        a[mf][2] = As[(m + grp) * 36 + k + 4 + qid];
        a[mf][3] = As[(m + 8 + grp) * 36 + k + 4 + qid];
      }
      unsigned b[4][2];
#pragma unroll
      for (int nf = 0; nf < 4; nf++) {
        int n = wn + nf * 8;
        b[nf][0] = Bs[(n + grp) * 36 + k + qid];
        b[nf][1] = Bs[(n + grp) * 36 + k + 4 + qid];
      }
#pragma unroll
      for (int mf = 0; mf < 4; mf++)
#pragma unroll
        for (int nf = 0; nf < 4; nf++)
          mma8(c[mf][nf], a[mf][0], a[mf][1], a[mf][2], a[mf][3], b[nf][0],
               b[nf][1]);
    }
    __syncthreads();
  }

#pragma unroll
  for (int mf = 0; mf < 4; mf++)
#pragma unroll
    for (int i = 0; i < 2; i++) {
      int row = m0 + wm + mf * 16 + grp + 8 * i;
#pragma unroll
      for (int nf = 0; nf < 4; nf++) {
        int e = wn + nf * 8 + 2 * qid;
        float2 v = {c[mf][nf][2 * i] + bo[n0 + e],
                    c[mf][nf][2 * i + 1] + bo[n0 + e + 1]};
        *(float2*)(out + (size_t)row * DN + n0 + e) = v;
      }
    }
}

// ---------------------------------------------------------------------------
extern "C" void kernel_launch(void* const* d_in, const int* in_sizes, int n_in,
                              void* d_out, int out_size) {
  (void)in_sizes; (void)n_in; (void)out_size;
  const float* data = (const float*)d_in[0];
  const float* Wq = (const float*)d_in[1];
  const float* Wk = (const float*)d_in[2];
  const float* Wv = (const float*)d_in[3];
  const float* Wo = (const float*)d_in[4];
  const float* bo = (const float*)d_in[5];
  float* out = (float*)d_out;

  const int attn_smem = (128 * 68 + 64 * 68 + 64 * 68 + 128 * 68) * 4;
  cudaFuncSetAttribute(attn_kernel, cudaFuncAttributeMaxDynamicSharedMemorySize,
                       attn_smem);

  qkv_kernel<<<dim3(BTN / 128, HN, 3), 128>>>(data, Wq, Wk, Wv);
  attn_kernel<<<dim3(TN / 128, BN * HN), 128, attn_smem>>>();
  proj_kernel<<<dim3(BTN / 128, DN / 64), 128>>>(Wo, bo, out);
}

// round 4
// speedup vs baseline: 7.9741x; 1.9701x over previous
#include <cuda_runtime.h>
#include <cuda_fp16.h>
#include <math.h>

#define BN 4
#define TN 2048
#define DN 1024
#define HN 16
#define HDN 64
#define BTN (BN * TN)
#define QK_SCALE 0.03125f  // 1/sqrt(1024)
#define SROW 72            // smem row stride in halves (36 words: conflict-free)

// Scratch (device globals)
__device__ __half g_datah[BTN * DN];
__device__ __half g_wqh[HN * DN * HDN];
__device__ __half g_wkh[HN * DN * HDN];
__device__ __half g_wvh[HN * DN * HDN];
__device__ __half g_woh[DN * DN];
__device__ __half g_q[BN * HN * TN * HDN];
__device__ __half g_k[BN * HN * TN * HDN];
__device__ __half g_v[BN * HN * TN * HDN];
__device__ __half g_attn[BTN * DN];

__device__ __forceinline__ unsigned sm_u32(const void* p) {
  return (unsigned)__cvta_generic_to_shared(p);
}

__device__ __forceinline__ void ldsm4(unsigned& r0, unsigned& r1, unsigned& r2,
                                      unsigned& r3, unsigned addr) {
  asm volatile("ldmatrix.sync.aligned.m8n8.x4.shared.b16 {%0,%1,%2,%3}, [%4];"
               : "=r"(r0), "=r"(r1), "=r"(r2), "=r"(r3)
               : "r"(addr));
}

__device__ __forceinline__ void ldsm4t(unsigned& r0, unsigned& r1, unsigned& r2,
                                       unsigned& r3, unsigned addr) {
  asm volatile(
      "ldmatrix.sync.aligned.m8n8.x4.trans.shared.b16 {%0,%1,%2,%3}, [%4];"
      : "=r"(r0), "=r"(r1), "=r"(r2), "=r"(r3)
      : "r"(addr));
}

__device__ __forceinline__ void mma16(float* c, unsigned a0, unsigned a1,
                                      unsigned a2, unsigned a3, unsigned b0,
                                      unsigned b1) {
  asm volatile(
      "mma.sync.aligned.m16n8k16.row.col.f32.f16.f16.f32 "
      "{%0,%1,%2,%3}, {%4,%5,%6,%7}, {%8,%9}, {%0,%1,%2,%3};"
      : "+f"(c[0]), "+f"(c[1]), "+f"(c[2]), "+f"(c[3])
      : "r"(a0), "r"(a1), "r"(a2), "r"(a3), "r"(b0), "r"(b1));
}

// ---------------------------------------------------------------------------
// Kernel 0: fp32 -> fp16 convert (grid-stride over float4)
// ---------------------------------------------------------------------------
__global__ __launch_bounds__(256) void cvt_kernel(const float* __restrict__ src,
                                                  __half* __restrict__ dst,
                                                  int n4) {
  int i = blockIdx.x * 256 + threadIdx.x;
  if (i < n4) {
    float4 v = *(const float4*)(src + (size_t)i * 4);
    __half2* d = (__half2*)(dst + (size_t)i * 4);
    d[0] = __floats2half2_rn(v.x, v.y);
    d[1] = __floats2half2_rn(v.z, v.w);
  }
}

// ---------------------------------------------------------------------------
// Kernel 1: QKV projections. C[128m,64n] = data[128,1024] @ W[1024,64].
// block=128 (4 warps, 2x2 grid, warp tile 64x32). A smem [m][k], B smem [k][n].
// A frags: ldmatrix; B frags: ldmatrix.trans ([k][n] storage).
// ---------------------------------------------------------------------------
__global__ __launch_bounds__(128) void qkv_kernel() {
  __shared__ __half As[128 * SROW];
  __shared__ __half Bs[64 * SROW];

  const int tid = threadIdx.x;
  const int w = tid >> 5, lane = tid & 31;
  const int tq = lane & 7, tm = lane >> 3;      // ldmatrix addr decomposition
  const int g = lane >> 2, q = lane & 3;        // mma fragment decomposition
  const int wm = (w >> 1) * 64, wn = (w & 1) * 32;
  const int h = blockIdx.y;
  const int m0 = blockIdx.x * 128;

  const __half* W;
  __half* out;
  float oscale;
  if (blockIdx.z == 0) { W = g_wqh; out = g_q; oscale = QK_SCALE; }
  else if (blockIdx.z == 1) { W = g_wkh; out = g_k; oscale = 1.0f; }
  else { W = g_wvh; out = g_v; oscale = 1.0f; }
  W += (size_t)h * DN * HDN;

  float c[4][4][4] = {};

  for (int k0 = 0; k0 < DN; k0 += 64) {
#pragma unroll
    for (int u = 0; u < 8; u++) {  // A: 128 x 64 halves
      int f = tid + u * 128;
      int row = f >> 3, cc = (f & 7) * 8;
      *(uint4*)(As + row * SROW + cc) =
          *(const uint4*)(g_datah + (size_t)(m0 + row) * DN + k0 + cc);
    }
#pragma unroll
    for (int u = 0; u < 4; u++) {  // B: 64k x 64n halves, [k][n]
      int f = tid + u * 128;
      int row = f >> 3, cc = (f & 7) * 8;
      *(uint4*)(Bs + row * SROW + cc) =
          *(const uint4*)(W + (size_t)(k0 + row) * HDN + cc);
    }
    __syncthreads();

#pragma unroll
    for (int kk = 0; kk < 4; kk++) {
      const int k = kk * 16;
      unsigned a[4][4];
#pragma unroll
      for (int mf = 0; mf < 4; mf++)
        ldsm4(a[mf][0], a[mf][1], a[mf][2], a[mf][3],
              sm_u32(As + (wm + mf * 16 + (tm & 1) * 8 + tq) * SROW + k +
                     (tm >> 1) * 8));
      unsigned b[4][2];
#pragma unroll
      for (int np = 0; np < 2; np++) {
        unsigned r0, r1, r2, r3;
        ldsm4t(r0, r1, r2, r3,
               sm_u32(Bs + (k + (tm & 1) * 8 + tq) * SROW + wn + np * 16 +
                      (tm >> 1) * 8));
        b[2 * np][0] = r0; b[2 * np][1] = r1;
        b[2 * np + 1][0] = r2; b[2 * np + 1][1] = r3;
      }
#pragma unroll
      for (int mf = 0; mf < 4; mf++)
#pragma unroll
        for (int nf = 0; nf < 4; nf++)
          mma16(c[mf][nf], a[mf][0], a[mf][1], a[mf][2], a[mf][3], b[nf][0],
                b[nf][1]);
    }
    __syncthreads();
  }

  const int b = m0 >> 11;
  const int tbase = m0 & (TN - 1);
#pragma unroll
  for (int mf = 0; mf < 4; mf++)
#pragma unroll
    for (int i = 0; i < 2; i++) {
      int t = tbase + wm + mf * 16 + g + 8 * i;
#pragma unroll
      for (int nf = 0; nf < 4; nf++) {
        int e = wn + nf * 8 + 2 * q;
        __half2 v = __floats2half2_rn(c[mf][nf][2 * i] * oscale,
                                      c[mf][nf][2 * i + 1] * oscale);
        *(__half2*)(out + ((size_t)((b * HN + h) * TN + t)) * HDN + e) = v;
      }
    }
}

// ---------------------------------------------------------------------------
// Kernel 2: causal flash attention. grid=(T/128, B*H), block=128.
// P stays in registers (fp16 C-frag == A-frag layout). No Ps smem.
// ---------------------------------------------------------------------------
__global__ __launch_bounds__(128) void attn_kernel() {
  __shared__ __half Qs[128 * SROW];
  __shared__ __half Ks[64 * SROW];  // [key][e]
  __shared__ __half Vs[64 * SROW];  // [s][e]

  const int tid = threadIdx.x;
  const int w = tid >> 5, lane = tid & 31;
  const int tq = lane & 7, tm = lane >> 3;
  const int g = lane >> 2, q = lane & 3;
  const int bh = blockIdx.y;
  const int m0 = blockIdx.x * 128;
  const int wrow = w * 32;

  const __half* qb = g_q + (size_t)bh * TN * HDN;
  const __half* kb = g_k + (size_t)bh * TN * HDN;
  const __half* vb = g_v + (size_t)bh * TN * HDN;

#pragma unroll
  for (int u = 0; u < 8; u++) {  // Q: 128 x 64 halves (pre-scaled)
    int f = tid + u * 128;
    int row = f >> 3, cc = (f & 7) * 8;
    *(uint4*)(Qs + row * SROW + cc) =
        *(const uint4*)(qb + (size_t)(m0 + row) * HDN + cc);
  }

  float o[2][8][4] = {};
  float m_i[2][2], l_i[2][2];
#pragma unroll
  for (int mf = 0; mf < 2; mf++)
#pragma unroll
    for (int i = 0; i < 2; i++) { m_i[mf][i] = -INFINITY; l_i[mf][i] = 0.f; }

  const int jmax = 2 * blockIdx.x + 1;
  for (int j = 0; j <= jmax; j++) {
    const int n0g = j * 64;
#pragma unroll
    for (int u = 0; u < 4; u++) {  // K, V tiles: 64 x 64 halves each
      int f = tid + u * 128;
      int row = f >> 3, cc = (f & 7) * 8;
      *(uint4*)(Ks + row * SROW + cc) =
          *(const uint4*)(kb + (size_t)(n0g + row) * HDN + cc);
      *(uint4*)(Vs + row * SROW + cc) =
          *(const uint4*)(vb + (size_t)(n0g + row) * HDN + cc);
    }
    __syncthreads();

    const bool active = (n0g <= m0 + wrow + 31);
    if (active) {
      // ---- S = Q K^T ----
      float s[2][8][4] = {};
#pragma unroll
      for (int kk = 0; kk < 4; kk++) {
        const int k = kk * 16;
        unsigned a[2][4];
#pragma unroll
        for (int mf = 0; mf < 2; mf++)
          ldsm4(a[mf][0], a[mf][1], a[mf][2], a[mf][3],
                sm_u32(Qs + (wrow + mf * 16 + (tm & 1) * 8 + tq) * SROW + k +
                       (tm >> 1) * 8));
#pragma unroll
        for (int np = 0; np < 4; np++) {  // K: [n][k] -> non-trans ldmatrix
          unsigned b0, b1, b2, b3;
          ldsm4(b0, b1, b2, b3,
                sm_u32(Ks + (np * 16 + (tm >> 1) * 8 + tq) * SROW + k +
                       (tm & 1) * 8));
#pragma unroll
          for (int mf = 0; mf < 2; mf++) {
            mma16(s[mf][2 * np], a[mf][0], a[mf][1], a[mf][2], a[mf][3], b0, b1);
            mma16(s[mf][2 * np + 1], a[mf][0], a[mf][1], a[mf][2], a[mf][3], b2,
                  b3);
          }
        }
      }

      // ---- causal mask (diagonal-touching tiles only) ----
      if (n0g + 63 > m0 + wrow) {
#pragma unroll
        for (int mf = 0; mf < 2; mf++)
#pragma unroll
          for (int i = 0; i < 2; i++) {
            int qrow = m0 + wrow + mf * 16 + g + 8 * i;
#pragma unroll
            for (int nf = 0; nf < 8; nf++) {
              int key = n0g + nf * 8 + 2 * q;
              if (key > qrow) s[mf][nf][2 * i] = -INFINITY;
              if (key + 1 > qrow) s[mf][nf][2 * i + 1] = -INFINITY;
            }
          }
      }

      // ---- online softmax; p -> half2 register fragments ----
      unsigned ph[2][8][2];
#pragma unroll
      for (int mf = 0; mf < 2; mf++)
#pragma unroll
        for (int i = 0; i < 2; i++) {
          float v = -INFINITY;
#pragma unroll
          for (int nf = 0; nf < 8; nf++)
            v = fmaxf(v, fmaxf(s[mf][nf][2 * i], s[mf][nf][2 * i + 1]));
          v = fmaxf(v, __shfl_xor_sync(0xffffffffu, v, 1));
          v = fmaxf(v, __shfl_xor_sync(0xffffffffu, v, 2));
          float mnew = fmaxf(m_i[mf][i], v);
          float corr = __expf(m_i[mf][i] - mnew);
          float rs = 0.f;
#pragma unroll
          for (int nf = 0; nf < 8; nf++) {
            float p0 = __expf(s[mf][nf][2 * i] - mnew);
            float p1 = __expf(s[mf][nf][2 * i + 1] - mnew);
            rs += p0 + p1;
            __half2 hp = __floats2half2_rn(p0, p1);
            ph[mf][nf][i] = *(unsigned*)&hp;
          }
          rs += __shfl_xor_sync(0xffffffffu, rs, 1);
          rs += __shfl_xor_sync(0xffffffffu, rs, 2);
          l_i[mf][i] = l_i[mf][i] * corr + rs;
          m_i[mf][i] = mnew;
#pragma unroll
          for (int nf = 0; nf < 8; nf++) {
            o[mf][nf][2 * i] *= corr;
            o[mf][nf][2 * i + 1] *= corr;
          }
        }

      // ---- O += P V  (A-frags straight from ph registers) ----
#pragma unroll
      for (int kk = 0; kk < 4; kk++) {
        const int k = kk * 16;
#pragma unroll
        for (int np = 0; np < 4; np++) {  // V: [k][n] -> trans ldmatrix
          unsigned b0, b1, b2, b3;
          ldsm4t(b0, b1, b2, b3,
                 sm_u32(Vs + (k + (tm & 1) * 8 + tq) * SROW + np * 16 +
                        (tm >> 1) * 8));
#pragma unroll
          for (int mf = 0; mf < 2; mf++) {
            mma16(o[mf][2 * np], ph[mf][2 * kk][0], ph[mf][2 * kk][1],
                  ph[mf][2 * kk + 1][0], ph[mf][2 * kk + 1][1], b0, b1);
            mma16(o[mf][2 * np + 1], ph[mf][2 * kk][0], ph[mf][2 * kk][1],
                  ph[mf][2 * kk + 1][0], ph[mf][2 * kk + 1][1], b2, b3);
          }
        }
      }
    }
    __syncthreads();
  }

  // Epilogue
  const int b = bh >> 4, h = bh & 15;
#pragma unroll
  for (int mf = 0; mf < 2; mf++)
#pragma unroll
    for (int i = 0; i < 2; i++) {
      int t = m0 + wrow + mf * 16 + g + 8 * i;
      float inv = 1.0f / l_i[mf][i];
#pragma unroll
      for (int nf = 0; nf < 8; nf++) {
        int e = nf * 8 + 2 * q;
        __half2 v = __floats2half2_rn(o[mf][nf][2 * i] * inv,
                                      o[mf][nf][2 * i + 1] * inv);
        *(__half2*)(g_attn + ((size_t)(b * TN + t)) * DN + h * HDN + e) = v;
      }
    }
}

// ---------------------------------------------------------------------------
// Kernel 3: out = attn @ Wo^T + bo. grid=(BT/128, D/64), block=128.
// A = g_attn [m][k]; B = Wo(half) [n][k] -> non-trans ldmatrix.
// ---------------------------------------------------------------------------
__global__ __launch_bounds__(128) void proj_kernel(const float* __restrict__ bo,
                                                   float* __restrict__ out) {
  __shared__ __half As[128 * SROW];
  __shared__ __half Bs[64 * SROW];  // [n][k]

  const int tid = threadIdx.x;
  const int w = tid >> 5, lane = tid & 31;
  const int tq = lane & 7, tm = lane >> 3;
  const int g = lane >> 2, q = lane & 3;
  const int wm = (w >> 1) * 64, wn = (w & 1) * 32;
  const int m0 = blockIdx.x * 128;
  const int n0 = blockIdx.y * 64;

  float c[4][4][4] = {};

  for (int k0 = 0; k0 < DN; k0 += 64) {
#pragma unroll
    for (int u = 0; u < 8; u++) {
      int f = tid + u * 128;
      int row = f >> 3, cc = (f & 7) * 8;
      *(uint4*)(As + row * SROW + cc) =
          *(const uint4*)(g_attn + (size_t)(m0 + row) * DN + k0 + cc);
    }
#pragma unroll
    for (int u = 0; u < 4; u++) {
      int f = tid + u * 128;
      int row = f >> 3, cc = (f & 7) * 8;
      *(uint4*)(Bs + row * SROW + cc) =
          *(const uint4*)(g_woh + (size_t)(n0 + row) * DN + k0 + cc);
    }
    __syncthreads();

#pragma unroll
    for (int kk = 0; kk < 4; kk++) {
      const int k = kk * 16;
      unsigned a[4][4];
#pragma unroll
      for (int mf = 0; mf < 4; mf++)
        ldsm4(a[mf][0], a[mf][1], a[mf][2], a[mf][3],
              sm_u32(As + (wm + mf * 16 + (tm & 1) * 8 + tq) * SROW + k +
                     (tm >> 1) * 8));
      unsigned b[4][2];
#pragma unroll
      for (int np = 0; np < 2; np++) {
        unsigned r0, r1, r2, r3;
        ldsm4(r0, r1, r2, r3,
              sm_u32(Bs + (wn + np * 16 + (tm >> 1) * 8 + tq) * SROW + k +
                     (tm & 1) * 8));
        b[2 * np][0] = r0; b[2 * np][1] = r1;
        b[2 * np + 1][0] = r2; b[2 * np + 1][1] = r3;
      }
#pragma unroll
      for (int mf = 0; mf < 4; mf++)
#pragma unroll
        for (int nf = 0; nf < 4; nf++)
          mma16(c[mf][nf], a[mf][0], a[mf][1], a[mf][2], a[mf][3], b[nf][0],
                b[nf][1]);
    }
    __syncthreads();
  }

#pragma unroll
  for (int mf = 0; mf < 4; mf++)
#pragma unroll
    for (int i = 0; i < 2; i++) {
      int row = m0 + wm + mf * 16 + g + 8 * i;
#pragma unroll
      for (int nf = 0; nf < 4; nf++) {
        int e = wn + nf * 8 + 2 * q;
        float2 v = {c[mf][nf][2 * i] + bo[n0 + e],
                    c[mf][nf][2 * i + 1] + bo[n0 + e + 1]};
        *(float2*)(out + (size_t)row * DN + n0 + e) = v;
      }
    }
}

// ---------------------------------------------------------------------------
extern "C" void kernel_launch(void* const* d_in, const int* in_sizes, int n_in,
                              void* d_out, int out_size) {
  (void)in_sizes; (void)n_in; (void)out_size;
  const float* data = (const float*)d_in[0];
  const float* Wq = (const float*)d_in[1];
  const float* Wk = (const float*)d_in[2];
  const float* Wv = (const float*)d_in[3];
  const float* Wo = (const float*)d_in[4];
  const float* bo = (const float*)d_in[5];
  float* out = (float*)d_out;

  __half* dsth;
  cudaGetSymbolAddress((void**)&dsth, g_datah);
  cvt_kernel<<<(BTN * DN / 4 + 255) / 256, 256>>>(data, dsth, BTN * DN / 4);
  cudaGetSymbolAddress((void**)&dsth, g_wqh);
  cvt_kernel<<<(HN * DN * HDN / 4 + 255) / 256, 256>>>(Wq, dsth,
                                                       HN * DN * HDN / 4);
  cudaGetSymbolAddress((void**)&dsth, g_wkh);
  cvt_kernel<<<(HN * DN * HDN / 4 + 255) / 256, 256>>>(Wk, dsth,
                                                       HN * DN * HDN / 4);
  cudaGetSymbolAddress((void**)&dsth, g_wvh);
  cvt_kernel<<<(HN * DN * HDN / 4 + 255) / 256, 256>>>(Wv, dsth,
                                                       HN * DN * HDN / 4);
  cudaGetSymbolAddress((void**)&dsth, g_woh);
  cvt_kernel<<<(DN * DN / 4 + 255) / 256, 256>>>(Wo, dsth, DN * DN / 4);

  qkv_kernel<<<dim3(BTN / 128, HN, 3), 128>>>();
  attn_kernel<<<dim3(TN / 128, BN * HN), 128>>>();
  proj_kernel<<<dim3(BTN / 128, DN / 64), 128>>>(bo, out);
}